// round 1
// baseline (speedup 1.0000x reference)
#include <cuda_runtime.h>
#include <cstdint>

#define BATCH   2
#define SEQ     2048
#define DMODEL  1024
#define DINNER  2048
#define DSTATE  16
#define DTRANK  64
#define M_TOK   (BATCH*SEQ)        // 4096 tokens
#define XZCOLS  (2*DINNER)         // 4096
#define XDBCOLS (DTRANK+2*DSTATE)  // 96
#define NCHUNK  16
#define CHUNK   (SEQ/NCHUNK)       // 128

// ---------------- scratch (static device memory; no allocs) ----------------
__device__ float g_xz   [(size_t)M_TOK*XZCOLS];     // in_proj out: [m][4096]
__device__ float g_u    [(size_t)M_TOK*DINNER];     // conv+silu out
__device__ float g_xdb  [(size_t)M_TOK*XDBCOLS];    // x_proj out
__device__ float g_delta[(size_t)M_TOK*DINNER];     // softplus(dt_proj)
__device__ float g_P    [(size_t)BATCH*DINNER*NCHUNK*DSTATE];
__device__ float g_Q    [(size_t)BATCH*DINNER*NCHUNK*DSTATE];
__device__ float g_Hin  [(size_t)BATCH*DINNER*NCHUNK*DSTATE];
__device__ float g_yg   [(size_t)M_TOK*DINNER];     // gated scan output
__device__ float g_tmp  [(size_t)M_TOK*DMODEL];     // out_proj result (pre-LN)

// ---------------- math helpers (FMA-pipe exp, no MUFU) ----------------
__device__ __forceinline__ float fast_exp(float x) {
    float t = x * 1.4426950408889634f;
    t = fminf(fmaxf(t, -125.0f), 125.0f);
    float fr = t + 12582912.0f;          // round-to-nearest via magic number
    float r  = fr - 12582912.0f;
    float f  = t - r;                    // in [-0.5, 0.5]
    float p = 1.5403530e-4f;
    p = fmaf(p, f, 1.3333558e-3f);
    p = fmaf(p, f, 9.6181291e-3f);
    p = fmaf(p, f, 5.5504109e-2f);
    p = fmaf(p, f, 2.4022651e-1f);
    p = fmaf(p, f, 6.9314718e-1f);
    p = fmaf(p, f, 1.0f);
    int ir = __float_as_int(fr) - 0x4B400000;   // integer part r
    float s = __int_as_float((ir + 127) << 23); // 2^r
    return p * s;
}

__device__ __forceinline__ float fast_sigmoid(float v) {
    return 1.0f / (1.0f + fast_exp(-v));
}

__device__ __forceinline__ float softplus_f(float v) {
    if (v > 15.0f) return v;
    return log1pf(fast_exp(v));
}

// ---------------- SGEMM 128x128x8, NT (both operands K-contiguous) --------
// C[m][n] = sum_k A[m*lda+k] * B[n*ldb+k]   (+bias[n], optional softplus)
template<int ACT>
__global__ __launch_bounds__(256)
void sgemm128(const float* __restrict__ A, int lda,
              const float* __restrict__ B, int ldb,
              const float* __restrict__ bias,
              float* __restrict__ C, int ldc, int K)
{
    __shared__ float As[8][128];
    __shared__ float Bs[8][128];
    const int tid = threadIdx.x;
    const int m0 = blockIdx.x * 128;
    const int n0 = blockIdx.y * 128;
    const int lr = tid >> 1;
    const int lc = (tid & 1) * 4;
    const float* Ag = A + (size_t)(m0 + lr) * lda + lc;
    const float* Bg = B + (size_t)(n0 + lr) * ldb + lc;
    const int tx = tid & 15;
    const int ty = tid >> 4;

    float acc[8][8];
#pragma unroll
    for (int i = 0; i < 8; i++)
#pragma unroll
        for (int j = 0; j < 8; j++) acc[i][j] = 0.0f;

    for (int k0 = 0; k0 < K; k0 += 8) {
        float4 av = *(const float4*)(Ag + k0);
        float4 bv = *(const float4*)(Bg + k0);
        As[lc+0][lr] = av.x; As[lc+1][lr] = av.y; As[lc+2][lr] = av.z; As[lc+3][lr] = av.w;
        Bs[lc+0][lr] = bv.x; Bs[lc+1][lr] = bv.y; Bs[lc+2][lr] = bv.z; Bs[lc+3][lr] = bv.w;
        __syncthreads();
#pragma unroll
        for (int k = 0; k < 8; k++) {
            float a[8], b[8];
            *(float4*)&a[0] = *(const float4*)&As[k][ty*8];
            *(float4*)&a[4] = *(const float4*)&As[k][ty*8+4];
            *(float4*)&b[0] = *(const float4*)&Bs[k][tx*8];
            *(float4*)&b[4] = *(const float4*)&Bs[k][tx*8+4];
#pragma unroll
            for (int i = 0; i < 8; i++)
#pragma unroll
                for (int j = 0; j < 8; j++)
                    acc[i][j] = fmaf(a[i], b[j], acc[i][j]);
        }
        __syncthreads();
    }

#pragma unroll
    for (int i = 0; i < 8; i++) {
        int m = m0 + ty*8 + i;
#pragma unroll
        for (int j = 0; j < 8; j++) {
            int n = n0 + tx*8 + j;
            float v = acc[i][j];
            if (bias) v += bias[n];
            if (ACT == 1) v = softplus_f(v);
            C[(size_t)m*ldc + n] = v;
        }
    }
}

// ---------------- skinny GEMM for x_proj: M=4096, N=96, K=2048 ------------
__global__ __launch_bounds__(256)
void sgemm_g2(const float* __restrict__ A,   // u [4096][2048]
              const float* __restrict__ B,   // W_xproj [96][2048]
              float* __restrict__ C)         // xdb [4096][96]
{
    __shared__ float As[16][32];
    __shared__ float Bs[16][96];
    const int tid = threadIdx.x;
    const int m0 = blockIdx.x * 32;
    const int tx = tid & 31;   // col group (3 cols)
    const int ty = tid >> 5;   // row group (4 rows)

    float acc[4][3];
#pragma unroll
    for (int i = 0; i < 4; i++)
#pragma unroll
        for (int j = 0; j < 3; j++) acc[i][j] = 0.0f;

    for (int k0 = 0; k0 < 2048; k0 += 16) {
#pragma unroll
        for (int t = 0; t < 2; t++) {
            int id = tid + t*256;
            int r = id >> 4, c = id & 15;
            As[c][r] = A[(size_t)(m0 + r)*2048 + k0 + c];
        }
#pragma unroll
        for (int t = 0; t < 6; t++) {
            int id = tid + t*256;
            int r = id >> 4, c = id & 15;
            Bs[c][r] = B[(size_t)r*2048 + k0 + c];
        }
        __syncthreads();
#pragma unroll
        for (int k = 0; k < 16; k++) {
            float a[4], b[3];
#pragma unroll
            for (int i = 0; i < 4; i++) a[i] = As[k][ty*4 + i];
#pragma unroll
            for (int j = 0; j < 3; j++) b[j] = Bs[k][tx*3 + j];
#pragma unroll
            for (int i = 0; i < 4; i++)
#pragma unroll
                for (int j = 0; j < 3; j++)
                    acc[i][j] = fmaf(a[i], b[j], acc[i][j]);
        }
        __syncthreads();
    }
#pragma unroll
    for (int i = 0; i < 4; i++)
#pragma unroll
        for (int j = 0; j < 3; j++)
            C[(size_t)(m0 + ty*4 + i)*XDBCOLS + tx*3 + j] = acc[i][j];
}

// ---------------- causal depthwise conv(4) + SiLU -------------------------
__global__ __launch_bounds__(256)
void conv_silu_kernel(const float* __restrict__ Wc, const float* __restrict__ bc)
{
    int idx = blockIdx.x * blockDim.x + threadIdx.x;
    if (idx >= M_TOK * DINNER) return;
    int e = idx & (DINNER - 1);
    int m = idx >> 11;
    int l = m & (SEQ - 1);
    int b = m >> 11;
    float acc = bc[e];
#pragma unroll
    for (int k = 0; k < 4; k++) {
        int l2 = l + k - 3;
        if (l2 >= 0)
            acc = fmaf(Wc[e*4 + k], g_xz[(size_t)(b*SEQ + l2)*XZCOLS + e], acc);
    }
    g_u[idx] = acc * fast_sigmoid(acc);
}

// ---------------- scan pass 1: per-chunk (P, Q) ---------------------------
__global__ __launch_bounds__(128)
void scan_chunk_kernel(const float* __restrict__ A_log)
{
    const int bid   = blockIdx.x;
    const int et    = bid & 15;
    const int chunk = (bid >> 4) & 15;
    const int b     = bid >> 8;
    const int e     = et*128 + threadIdx.x;

    __shared__ float4 Bs[CHUNK][4];
    {
        int s = threadIdx.x;
        size_t m = (size_t)b*SEQ + chunk*CHUNK + s;
        const float4* p4 = (const float4*)&g_xdb[m*XDBCOLS + DTRANK];
        Bs[s][0] = p4[0]; Bs[s][1] = p4[1]; Bs[s][2] = p4[2]; Bs[s][3] = p4[3];
    }
    __syncthreads();

    float An[DSTATE];
#pragma unroll
    for (int n = 0; n < DSTATE; n++) An[n] = -fast_exp(A_log[e*DSTATE + n]);

    float p[DSTATE], q[DSTATE];
#pragma unroll
    for (int n = 0; n < DSTATE; n++) { p[n] = 1.0f; q[n] = 0.0f; }

    const int mbase = b*SEQ + chunk*CHUNK;
    for (int s = 0; s < CHUNK; s++) {
        size_t off = (size_t)(mbase + s)*DINNER + e;
        float d  = g_delta[off];
        float du = d * g_u[off];
        const float* Bp = (const float*)&Bs[s][0];
#pragma unroll
        for (int n = 0; n < DSTATE; n++) {
            float dA = fast_exp(d * An[n]);
            q[n] = fmaf(dA, q[n], du * Bp[n]);
            p[n] *= dA;
        }
    }
    const int c = b*DINNER + e;
    size_t ob = ((size_t)c*NCHUNK + chunk)*DSTATE;
#pragma unroll
    for (int n = 0; n < DSTATE; n++) { g_P[ob + n] = p[n]; g_Q[ob + n] = q[n]; }
}

// ---------------- scan pass 2: cross-chunk prefix -------------------------
__global__ __launch_bounds__(256)
void scan_prefix_kernel()
{
    int idx = blockIdx.x * blockDim.x + threadIdx.x;  // c*16 + n
    if (idx >= BATCH*DINNER*DSTATE) return;
    int c = idx >> 4, n = idx & 15;
    float h = 0.0f;
#pragma unroll
    for (int ch = 0; ch < NCHUNK; ch++) {
        size_t o = ((size_t)c*NCHUNK + ch)*DSTATE + n;
        g_Hin[o] = h;
        h = fmaf(g_P[o], h, g_Q[o]);
    }
}

// ---------------- scan pass 3: replay + D-skip + SiLU gate ----------------
__global__ __launch_bounds__(128)
void scan_apply_kernel(const float* __restrict__ A_log,
                       const float* __restrict__ Dskip)
{
    const int bid   = blockIdx.x;
    const int et    = bid & 15;
    const int chunk = (bid >> 4) & 15;
    const int b     = bid >> 8;
    const int e     = et*128 + threadIdx.x;

    __shared__ float4 Bs[CHUNK][4];
    __shared__ float4 Cs[CHUNK][4];
    {
        int s = threadIdx.x;
        size_t m = (size_t)b*SEQ + chunk*CHUNK + s;
        const float4* p4 = (const float4*)&g_xdb[m*XDBCOLS + DTRANK];
        Bs[s][0] = p4[0]; Bs[s][1] = p4[1]; Bs[s][2] = p4[2]; Bs[s][3] = p4[3];
        Cs[s][0] = p4[4]; Cs[s][1] = p4[5]; Cs[s][2] = p4[6]; Cs[s][3] = p4[7];
    }
    __syncthreads();

    float An[DSTATE];
#pragma unroll
    for (int n = 0; n < DSTATE; n++) An[n] = -fast_exp(A_log[e*DSTATE + n]);

    const int c = b*DINNER + e;
    float h[DSTATE];
    {
        size_t ob = ((size_t)c*NCHUNK + chunk)*DSTATE;
#pragma unroll
        for (int n = 0; n < DSTATE; n++) h[n] = g_Hin[ob + n];
    }
    const float dsk = Dskip[e];
    const int mbase = b*SEQ + chunk*CHUNK;

    for (int s = 0; s < CHUNK; s++) {
        size_t off = (size_t)(mbase + s)*DINNER + e;
        float d  = g_delta[off];
        float uu = g_u[off];
        float du = d * uu;
        const float* Bp = (const float*)&Bs[s][0];
        const float* Cp = (const float*)&Cs[s][0];
        float y = 0.0f;
#pragma unroll
        for (int n = 0; n < DSTATE; n++) {
            float dA = fast_exp(d * An[n]);
            h[n] = fmaf(dA, h[n], du * Bp[n]);
            y = fmaf(h[n], Cp[n], y);
        }
        y = fmaf(uu, dsk, y);
        float zv = g_xz[(size_t)(mbase + s)*XZCOLS + DINNER + e];
        g_yg[off] = y * zv * fast_sigmoid(zv);
    }
}

// ---------------- residual + LayerNorm ------------------------------------
__global__ __launch_bounds__(256)
void ln_kernel(const float* __restrict__ x, const float* __restrict__ gamma,
               const float* __restrict__ beta, float* __restrict__ out)
{
    const int m = blockIdx.x;
    __shared__ float buf[DMODEL];
    __shared__ float rs[2][8];
    float s1 = 0.0f, s2 = 0.0f;
#pragma unroll
    for (int i = 0; i < 4; i++) {
        int d = threadIdx.x + i*256;
        float v = g_tmp[(size_t)m*DMODEL + d] + x[(size_t)m*DMODEL + d];
        buf[d] = v;
        s1 += v; s2 += v*v;
    }
#pragma unroll
    for (int o = 16; o; o >>= 1) {
        s1 += __shfl_xor_sync(0xFFFFFFFFu, s1, o);
        s2 += __shfl_xor_sync(0xFFFFFFFFu, s2, o);
    }
    int w = threadIdx.x >> 5, lane = threadIdx.x & 31;
    if (lane == 0) { rs[0][w] = s1; rs[1][w] = s2; }
    __syncthreads();
    if (threadIdx.x == 0) {
        float a = 0.0f, b2 = 0.0f;
#pragma unroll
        for (int k = 0; k < 8; k++) { a += rs[0][k]; b2 += rs[1][k]; }
        rs[0][0] = a; rs[1][0] = b2;
    }
    __syncthreads();
    float mu  = rs[0][0] * (1.0f/DMODEL);
    float var = rs[1][0] * (1.0f/DMODEL) - mu*mu;
    float rstd = rsqrtf(var + 1e-5f);
#pragma unroll
    for (int i = 0; i < 4; i++) {
        int d = threadIdx.x + i*256;
        float v = buf[d];
        out[(size_t)m*DMODEL + d] = (v - mu)*rstd*gamma[d] + beta[d];
    }
}

// ---------------- launcher -------------------------------------------------
extern "C" void kernel_launch(void* const* d_in, const int* in_sizes, int n_in,
                              void* d_out, int out_size)
{
    const float* x       = (const float*)d_in[0];
    const float* W_in    = (const float*)d_in[1];
    const float* W_conv  = (const float*)d_in[2];
    const float* b_conv  = (const float*)d_in[3];
    const float* W_xproj = (const float*)d_in[4];
    const float* W_dt    = (const float*)d_in[5];
    const float* b_dt    = (const float*)d_in[6];
    const float* A_log   = (const float*)d_in[7];
    const float* D_skip  = (const float*)d_in[8];
    const float* W_out   = (const float*)d_in[9];
    const float* gamma   = (const float*)d_in[10];
    const float* beta    = (const float*)d_in[11];
    float* out = (float*)d_out;

    float *p_xz, *p_u, *p_xdb, *p_delta, *p_yg, *p_tmp;
    cudaGetSymbolAddress((void**)&p_xz,    g_xz);
    cudaGetSymbolAddress((void**)&p_u,     g_u);
    cudaGetSymbolAddress((void**)&p_xdb,   g_xdb);
    cudaGetSymbolAddress((void**)&p_delta, g_delta);
    cudaGetSymbolAddress((void**)&p_yg,    g_yg);
    cudaGetSymbolAddress((void**)&p_tmp,   g_tmp);

    // 1) in_proj: xz[4096][4096] = x[4096][1024] @ W_in^T
    sgemm128<0><<<dim3(32, 32), 256>>>(x, DMODEL, W_in, DMODEL, nullptr,
                                       p_xz, XZCOLS, DMODEL);
    // 2) causal depthwise conv + SiLU -> u
    conv_silu_kernel<<<(M_TOK*DINNER)/256, 256>>>(W_conv, b_conv);
    // 3) x_proj: xdb[4096][96] = u @ W_xproj^T
    sgemm_g2<<<128, 256>>>(p_u, W_xproj, p_xdb);
    // 4) dt_proj + bias + softplus -> delta[4096][2048]
    sgemm128<1><<<dim3(32, 16), 256>>>(p_xdb, XDBCOLS, W_dt, DTRANK, b_dt,
                                       p_delta, DINNER, DTRANK);
    // 5) selective scan (chunked) + gate
    scan_chunk_kernel<<<BATCH*NCHUNK*16, 128>>>(A_log);
    scan_prefix_kernel<<<(BATCH*DINNER*DSTATE)/256, 256>>>();
    scan_apply_kernel<<<BATCH*NCHUNK*16, 128>>>(A_log, D_skip);
    // 6) out_proj: tmp[4096][1024] = yg @ W_out^T
    sgemm128<0><<<dim3(32, 8), 256>>>(p_yg, DINNER, W_out, DINNER, nullptr,
                                      p_tmp, DMODEL, DINNER);
    // 7) residual + LayerNorm
    ln_kernel<<<M_TOK, 256>>>(x, gamma, beta, out);
}

// round 3
// speedup vs baseline: 1.8519x; 1.8519x over previous
#include <cuda_runtime.h>
#include <cuda_bf16.h>
#include <cstdint>

#define BATCH   2
#define SEQ     2048
#define DMODEL  1024
#define DINNER  2048
#define DSTATE  16
#define DTRANK  64
#define M_TOK   (BATCH*SEQ)        // 4096 tokens
#define XZCOLS  (2*DINNER)         // 4096
#define XDBCOLS (DTRANK+2*DSTATE)  // 96
#define NCHUNK  16
#define CHUNK   (SEQ/NCHUNK)       // 128

// ---------------- scratch (static device memory; no allocs) ----------------
__device__ float g_xz   [(size_t)M_TOK*XZCOLS];     // in_proj out: [m][4096]
__device__ float g_u    [(size_t)M_TOK*DINNER];     // conv+silu out
__device__ float g_xdb  [(size_t)M_TOK*XDBCOLS];    // x_proj out
__device__ float g_delta[(size_t)M_TOK*DINNER];     // softplus(dt_proj)
__device__ float g_P    [(size_t)BATCH*DINNER*NCHUNK*DSTATE];
__device__ float g_Q    [(size_t)BATCH*DINNER*NCHUNK*DSTATE];
__device__ float g_Hin  [(size_t)BATCH*DINNER*NCHUNK*DSTATE];
__device__ float g_tmp  [(size_t)M_TOK*DMODEL];     // out_proj result (pre-LN)

// bf16 hi/lo split operands for tensor-core GEMMs
__device__ __nv_bfloat16 g_xhi [(size_t)M_TOK*DMODEL];
__device__ __nv_bfloat16 g_xlo [(size_t)M_TOK*DMODEL];
__device__ __nv_bfloat16 g_wih [(size_t)XZCOLS*DMODEL];
__device__ __nv_bfloat16 g_wil [(size_t)XZCOLS*DMODEL];
__device__ __nv_bfloat16 g_woh [(size_t)DMODEL*DINNER];
__device__ __nv_bfloat16 g_wol [(size_t)DMODEL*DINNER];
__device__ __nv_bfloat16 g_ygh [(size_t)M_TOK*DINNER];
__device__ __nv_bfloat16 g_ygl [(size_t)M_TOK*DINNER];

// ---------------- math helpers (FMA-pipe exp, no MUFU) ----------------
__device__ __forceinline__ float fast_exp(float x) {
    float t = x * 1.4426950408889634f;
    t = fminf(fmaxf(t, -125.0f), 125.0f);
    float fr = t + 12582912.0f;          // round-to-nearest via magic number
    float r  = fr - 12582912.0f;
    float f  = t - r;                    // in [-0.5, 0.5]
    float p = 1.5403530e-4f;
    p = fmaf(p, f, 1.3333558e-3f);
    p = fmaf(p, f, 9.6181291e-3f);
    p = fmaf(p, f, 5.5504109e-2f);
    p = fmaf(p, f, 2.4022651e-1f);
    p = fmaf(p, f, 6.9314718e-1f);
    p = fmaf(p, f, 1.0f);
    int ir = __float_as_int(fr) - 0x4B400000;   // integer part r
    float s = __int_as_float((ir + 127) << 23); // 2^r
    return p * s;
}

__device__ __forceinline__ float fast_sigmoid(float v) {
    return 1.0f / (1.0f + fast_exp(-v));
}

__device__ __forceinline__ float softplus_f(float v) {
    if (v > 15.0f) return v;
    return log1pf(fast_exp(v));
}

__device__ __forceinline__ uint32_t smem_u32(const void* p) {
    uint32_t a;
    asm("{ .reg .u64 t; cvta.to.shared.u64 t, %1; cvt.u32.u64 %0, t; }"
        : "=r"(a) : "l"(p));
    return a;
}

// ---------------- HMMA (mma.sync) bf16 GEMM, baseline PTX ISA -------------
// C[m][n] = sum_k A[m][k]*B[n][k] with A,B bf16 hi/lo split (3 MMA passes).
// CTA tile 128x128, 256 threads, K-stage 32, cp.async double buffer.
#define LDSM4(r0, r1, r2, r3, a) \
    asm volatile("ldmatrix.sync.aligned.m8n8.x4.shared.b16 {%0,%1,%2,%3}, [%4];" \
        : "=r"(r0), "=r"(r1), "=r"(r2), "=r"(r3) : "r"(a))

#define MMA16816(cc, aa, b0, b1) \
    asm volatile("mma.sync.aligned.m16n8k16.row.col.f32.bf16.bf16.f32 " \
        "{%0,%1,%2,%3}, {%4,%5,%6,%7}, {%8,%9}, {%0,%1,%2,%3};" \
        : "+f"((cc)[0]), "+f"((cc)[1]), "+f"((cc)[2]), "+f"((cc)[3]) \
        : "r"((aa)[0]), "r"((aa)[1]), "r"((aa)[2]), "r"((aa)[3]), \
          "r"(b0), "r"(b1))

#define CPASYNC16(saddr, gaddr) \
    asm volatile("cp.async.ca.shared.global [%0], [%1], 16;" \
        :: "r"(saddr), "l"(gaddr))

#define ARR_BYTES 10240        // 128 rows * 80B (64B data + 16B pad)
#define STAGE_BYTES (4*ARR_BYTES)
#define HG_SMEM (2*STAGE_BYTES)   // 81920

__global__ __launch_bounds__(256, 1)
void hmma_gemm(const __nv_bfloat16* __restrict__ Ahi, const __nv_bfloat16* __restrict__ Alo,
               const __nv_bfloat16* __restrict__ Bhi, const __nv_bfloat16* __restrict__ Blo,
               float* __restrict__ C, int K, int ldc)
{
    extern __shared__ char smem_raw[];
    const uint32_t sbase = smem_u32(smem_raw);
    const int tid  = threadIdx.x;
    const int lane = tid & 31;
    const int wid  = tid >> 5;
    const int m0 = blockIdx.x * 128, n0 = blockIdx.y * 128;
    const int wm = (wid >> 2) * 64, wn = (wid & 3) * 32;

    // ldmatrix per-lane row/byte offsets
    const uint32_t a_r = (lane & 7) + ((lane >> 3) & 1) * 8;
    const uint32_t a_b = (lane >> 4) * 16;
    const uint32_t b_r = (lane & 7) + ((lane >> 4) & 1) * 8;
    const uint32_t b_b = ((lane >> 3) & 1) * 16;

    float c[4][4][4];
#pragma unroll
    for (int i = 0; i < 4; i++)
#pragma unroll
        for (int j = 0; j < 4; j++)
#pragma unroll
            for (int r = 0; r < 4; r++) c[i][j][r] = 0.0f;

    // per-thread cp.async assignments: 512 16B-chunks per array, 2 per thread
    const int nst = K >> 5;

#define DO_LOAD(s, bf) do {                                                  \
    int _k0 = (s) * 32;                                                      \
    uint32_t _st = sbase + (bf) * STAGE_BYTES;                               \
    _Pragma("unroll")                                                        \
    for (int _t = 0; _t < 2; _t++) {                                         \
        int _cc = tid + _t * 256;                                            \
        int _row = _cc >> 2, _ci = _cc & 3;                                  \
        uint32_t _so = _row * 80 + _ci * 16;                                 \
        size_t _ga = (size_t)(m0 + _row) * K + _k0 + _ci * 8;                \
        size_t _gb = (size_t)(n0 + _row) * K + _k0 + _ci * 8;                \
        CPASYNC16(_st + _so,                 Ahi + _ga);                     \
        CPASYNC16(_st + ARR_BYTES + _so,     Alo + _ga);                     \
        CPASYNC16(_st + 2*ARR_BYTES + _so,   Bhi + _gb);                     \
        CPASYNC16(_st + 3*ARR_BYTES + _so,   Blo + _gb);                     \
    }                                                                        \
    asm volatile("cp.async.commit_group;" ::: "memory");                     \
} while (0)

    DO_LOAD(0, 0);

    for (int s = 0; s < nst; s++) {
        const int bf = s & 1;
        if (s + 1 < nst) {
            DO_LOAD(s + 1, bf ^ 1);
            asm volatile("cp.async.wait_group 1;" ::: "memory");
        } else {
            asm volatile("cp.async.wait_group 0;" ::: "memory");
        }
        __syncthreads();

        const uint32_t st = sbase + bf * STAGE_BYTES;
#pragma unroll
        for (int ks = 0; ks < 2; ks++) {
            uint32_t ah[4][4], al[4][4], bh[4][2], bl[4][2];
#pragma unroll
            for (int mi = 0; mi < 4; mi++) {
                uint32_t ad = st + (wm + mi*16 + a_r) * 80 + ks * 32 + a_b;
                LDSM4(ah[mi][0], ah[mi][1], ah[mi][2], ah[mi][3], ad);
                LDSM4(al[mi][0], al[mi][1], al[mi][2], al[mi][3], ad + ARR_BYTES);
            }
#pragma unroll
            for (int nj = 0; nj < 2; nj++) {
                uint32_t bd = st + 2*ARR_BYTES + (wn + nj*16 + b_r) * 80 + ks * 32 + b_b;
                uint32_t r0, r1, r2, r3;
                LDSM4(r0, r1, r2, r3, bd);
                bh[nj*2][0] = r0; bh[nj*2][1] = r1;
                bh[nj*2+1][0] = r2; bh[nj*2+1][1] = r3;
                LDSM4(r0, r1, r2, r3, bd + ARR_BYTES);
                bl[nj*2][0] = r0; bl[nj*2][1] = r1;
                bl[nj*2+1][0] = r2; bl[nj*2+1][1] = r3;
            }
#pragma unroll
            for (int mi = 0; mi < 4; mi++) {
#pragma unroll
                for (int nt = 0; nt < 4; nt++) {
                    MMA16816(c[mi][nt], ah[mi], bh[nt][0], bh[nt][1]);
                    MMA16816(c[mi][nt], ah[mi], bl[nt][0], bl[nt][1]);
                    MMA16816(c[mi][nt], al[mi], bh[nt][0], bh[nt][1]);
                }
            }
        }
        __syncthreads();
    }

#pragma unroll
    for (int mi = 0; mi < 4; mi++) {
        int row = m0 + wm + mi*16 + (lane >> 2);
#pragma unroll
        for (int nt = 0; nt < 4; nt++) {
            int col = n0 + wn + nt*8 + (lane & 3)*2;
            *(float2*)&C[(size_t)row * ldc + col] =
                make_float2(c[mi][nt][0], c[mi][nt][1]);
            *(float2*)&C[(size_t)(row + 8) * ldc + col] =
                make_float2(c[mi][nt][2], c[mi][nt][3]);
        }
    }
}

// ---------------- fp32 -> bf16 hi/lo converter ----------------------------
__global__ __launch_bounds__(256)
void cvt_kernel(const float* __restrict__ src, __nv_bfloat16* __restrict__ hi,
                __nv_bfloat16* __restrict__ lo, int n4)
{
    int i = blockIdx.x * blockDim.x + threadIdx.x;
    if (i >= n4) return;
    float4 v = ((const float4*)src)[i];
    __nv_bfloat16 h0 = __float2bfloat16(v.x), h1 = __float2bfloat16(v.y);
    __nv_bfloat16 h2 = __float2bfloat16(v.z), h3 = __float2bfloat16(v.w);
    __nv_bfloat16 l0 = __float2bfloat16(v.x - __bfloat162float(h0));
    __nv_bfloat16 l1 = __float2bfloat16(v.y - __bfloat162float(h1));
    __nv_bfloat16 l2 = __float2bfloat16(v.z - __bfloat162float(h2));
    __nv_bfloat16 l3 = __float2bfloat16(v.w - __bfloat162float(h3));
    ((__nv_bfloat162*)hi)[i*2+0] = __nv_bfloat162(h0, h1);
    ((__nv_bfloat162*)hi)[i*2+1] = __nv_bfloat162(h2, h3);
    ((__nv_bfloat162*)lo)[i*2+0] = __nv_bfloat162(l0, l1);
    ((__nv_bfloat162*)lo)[i*2+1] = __nv_bfloat162(l2, l3);
}

// ---------------- SGEMM 128x128x8 (kept for dt_proj) ----------------------
template<int ACT>
__global__ __launch_bounds__(256)
void sgemm128(const float* __restrict__ A, int lda,
              const float* __restrict__ B, int ldb,
              const float* __restrict__ bias,
              float* __restrict__ C, int ldc, int K)
{
    __shared__ float As[8][128];
    __shared__ float Bs[8][128];
    const int tid = threadIdx.x;
    const int m0 = blockIdx.x * 128;
    const int n0 = blockIdx.y * 128;
    const int lr = tid >> 1;
    const int lc = (tid & 1) * 4;
    const float* Ag = A + (size_t)(m0 + lr) * lda + lc;
    const float* Bg = B + (size_t)(n0 + lr) * ldb + lc;
    const int tx = tid & 15;
    const int ty = tid >> 4;

    float acc[8][8];
#pragma unroll
    for (int i = 0; i < 8; i++)
#pragma unroll
        for (int j = 0; j < 8; j++) acc[i][j] = 0.0f;

    for (int k0 = 0; k0 < K; k0 += 8) {
        float4 av = *(const float4*)(Ag + k0);
        float4 bv = *(const float4*)(Bg + k0);
        As[lc+0][lr] = av.x; As[lc+1][lr] = av.y; As[lc+2][lr] = av.z; As[lc+3][lr] = av.w;
        Bs[lc+0][lr] = bv.x; Bs[lc+1][lr] = bv.y; Bs[lc+2][lr] = bv.z; Bs[lc+3][lr] = bv.w;
        __syncthreads();
#pragma unroll
        for (int k = 0; k < 8; k++) {
            float a[8], b[8];
            *(float4*)&a[0] = *(const float4*)&As[k][ty*8];
            *(float4*)&a[4] = *(const float4*)&As[k][ty*8+4];
            *(float4*)&b[0] = *(const float4*)&Bs[k][tx*8];
            *(float4*)&b[4] = *(const float4*)&Bs[k][tx*8+4];
#pragma unroll
            for (int i = 0; i < 8; i++)
#pragma unroll
                for (int j = 0; j < 8; j++)
                    acc[i][j] = fmaf(a[i], b[j], acc[i][j]);
        }
        __syncthreads();
    }

#pragma unroll
    for (int i = 0; i < 8; i++) {
        int m = m0 + ty*8 + i;
#pragma unroll
        for (int j = 0; j < 8; j++) {
            int n = n0 + tx*8 + j;
            float v = acc[i][j];
            if (bias) v += bias[n];
            if (ACT == 1) v = softplus_f(v);
            C[(size_t)m*ldc + n] = v;
        }
    }
}

// ---------------- skinny GEMM for x_proj: M=4096, N=96, K=2048 ------------
__global__ __launch_bounds__(256)
void sgemm_g2(const float* __restrict__ A,   // u [4096][2048]
              const float* __restrict__ B,   // W_xproj [96][2048]
              float* __restrict__ C)         // xdb [4096][96]
{
    __shared__ float As[16][32];
    __shared__ float Bs[16][96];
    const int tid = threadIdx.x;
    const int m0 = blockIdx.x * 32;
    const int tx = tid & 31;   // col group (3 cols)
    const int ty = tid >> 5;   // row group (4 rows)

    float acc[4][3];
#pragma unroll
    for (int i = 0; i < 4; i++)
#pragma unroll
        for (int j = 0; j < 3; j++) acc[i][j] = 0.0f;

    for (int k0 = 0; k0 < 2048; k0 += 16) {
#pragma unroll
        for (int t = 0; t < 2; t++) {
            int id = tid + t*256;
            int r = id >> 4, c = id & 15;
            As[c][r] = A[(size_t)(m0 + r)*2048 + k0 + c];
        }
#pragma unroll
        for (int t = 0; t < 6; t++) {
            int id = tid + t*256;
            int r = id >> 4, c = id & 15;
            Bs[c][r] = B[(size_t)r*2048 + k0 + c];
        }
        __syncthreads();
#pragma unroll
        for (int k = 0; k < 16; k++) {
            float a[4], b[3];
#pragma unroll
            for (int i = 0; i < 4; i++) a[i] = As[k][ty*4 + i];
#pragma unroll
            for (int j = 0; j < 3; j++) b[j] = Bs[k][tx*3 + j];
#pragma unroll
            for (int i = 0; i < 4; i++)
#pragma unroll
                for (int j = 0; j < 3; j++)
                    acc[i][j] = fmaf(a[i], b[j], acc[i][j]);
        }
        __syncthreads();
    }
#pragma unroll
    for (int i = 0; i < 4; i++)
#pragma unroll
        for (int j = 0; j < 3; j++)
            C[(size_t)(m0 + ty*4 + i)*XDBCOLS + tx*3 + j] = acc[i][j];
}

// ---------------- causal depthwise conv(4) + SiLU -------------------------
__global__ __launch_bounds__(256)
void conv_silu_kernel(const float* __restrict__ Wc, const float* __restrict__ bc)
{
    int idx = blockIdx.x * blockDim.x + threadIdx.x;
    if (idx >= M_TOK * DINNER) return;
    int e = idx & (DINNER - 1);
    int m = idx >> 11;
    int l = m & (SEQ - 1);
    int b = m >> 11;
    float acc = bc[e];
#pragma unroll
    for (int k = 0; k < 4; k++) {
        int l2 = l + k - 3;
        if (l2 >= 0)
            acc = fmaf(Wc[e*4 + k], g_xz[(size_t)(b*SEQ + l2)*XZCOLS + e], acc);
    }
    g_u[idx] = acc * fast_sigmoid(acc);
}

// ---------------- scan pass 1: per-chunk (P, Q) ---------------------------
__global__ __launch_bounds__(128)
void scan_chunk_kernel(const float* __restrict__ A_log)
{
    const int bid   = blockIdx.x;
    const int et    = bid & 15;
    const int chunk = (bid >> 4) & 15;
    const int b     = bid >> 8;
    const int e     = et*128 + threadIdx.x;

    __shared__ float4 Bs[CHUNK][4];
    {
        int s = threadIdx.x;
        size_t m = (size_t)b*SEQ + chunk*CHUNK + s;
        const float4* p4 = (const float4*)&g_xdb[m*XDBCOLS + DTRANK];
        Bs[s][0] = p4[0]; Bs[s][1] = p4[1]; Bs[s][2] = p4[2]; Bs[s][3] = p4[3];
    }
    __syncthreads();

    float An[DSTATE];
#pragma unroll
    for (int n = 0; n < DSTATE; n++) An[n] = -fast_exp(A_log[e*DSTATE + n]);

    float p[DSTATE], q[DSTATE];
#pragma unroll
    for (int n = 0; n < DSTATE; n++) { p[n] = 1.0f; q[n] = 0.0f; }

    const int mbase = b*SEQ + chunk*CHUNK;
    for (int s = 0; s < CHUNK; s++) {
        size_t off = (size_t)(mbase + s)*DINNER + e;
        float d  = g_delta[off];
        float du = d * g_u[off];
        const float* Bp = (const float*)&Bs[s][0];
#pragma unroll
        for (int n = 0; n < DSTATE; n++) {
            float dA = fast_exp(d * An[n]);
            q[n] = fmaf(dA, q[n], du * Bp[n]);
            p[n] *= dA;
        }
    }
    const int c = b*DINNER + e;
    size_t ob = ((size_t)c*NCHUNK + chunk)*DSTATE;
#pragma unroll
    for (int n = 0; n < DSTATE; n++) { g_P[ob + n] = p[n]; g_Q[ob + n] = q[n]; }
}

// ---------------- scan pass 2: cross-chunk prefix -------------------------
__global__ __launch_bounds__(256)
void scan_prefix_kernel()
{
    int idx = blockIdx.x * blockDim.x + threadIdx.x;  // c*16 + n
    if (idx >= BATCH*DINNER*DSTATE) return;
    int c = idx >> 4, n = idx & 15;
    float h = 0.0f;
#pragma unroll
    for (int ch = 0; ch < NCHUNK; ch++) {
        size_t o = ((size_t)c*NCHUNK + ch)*DSTATE + n;
        g_Hin[o] = h;
        h = fmaf(g_P[o], h, g_Q[o]);
    }
}

// ---------------- scan pass 3: replay + D-skip + SiLU gate ----------------
__global__ __launch_bounds__(128)
void scan_apply_kernel(const float* __restrict__ A_log,
                       const float* __restrict__ Dskip)
{
    const int bid   = blockIdx.x;
    const int et    = bid & 15;
    const int chunk = (bid >> 4) & 15;
    const int b     = bid >> 8;
    const int e     = et*128 + threadIdx.x;

    __shared__ float4 Bs[CHUNK][4];
    __shared__ float4 Cs[CHUNK][4];
    {
        int s = threadIdx.x;
        size_t m = (size_t)b*SEQ + chunk*CHUNK + s;
        const float4* p4 = (const float4*)&g_xdb[m*XDBCOLS + DTRANK];
        Bs[s][0] = p4[0]; Bs[s][1] = p4[1]; Bs[s][2] = p4[2]; Bs[s][3] = p4[3];
        Cs[s][0] = p4[4]; Cs[s][1] = p4[5]; Cs[s][2] = p4[6]; Cs[s][3] = p4[7];
    }
    __syncthreads();

    float An[DSTATE];
#pragma unroll
    for (int n = 0; n < DSTATE; n++) An[n] = -fast_exp(A_log[e*DSTATE + n]);

    const int c = b*DINNER + e;
    float h[DSTATE];
    {
        size_t ob = ((size_t)c*NCHUNK + chunk)*DSTATE;
#pragma unroll
        for (int n = 0; n < DSTATE; n++) h[n] = g_Hin[ob + n];
    }
    const float dsk = Dskip[e];
    const int mbase = b*SEQ + chunk*CHUNK;

    for (int s = 0; s < CHUNK; s++) {
        size_t off = (size_t)(mbase + s)*DINNER + e;
        float d  = g_delta[off];
        float uu = g_u[off];
        float du = d * uu;
        const float* Bp = (const float*)&Bs[s][0];
        const float* Cp = (const float*)&Cs[s][0];
        float y = 0.0f;
#pragma unroll
        for (int n = 0; n < DSTATE; n++) {
            float dA = fast_exp(d * An[n]);
            h[n] = fmaf(dA, h[n], du * Bp[n]);
            y = fmaf(h[n], Cp[n], y);
        }
        y = fmaf(uu, dsk, y);
        float zv = g_xz[(size_t)(mbase + s)*XZCOLS + DINNER + e];
        float val = y * zv * fast_sigmoid(zv);
        __nv_bfloat16 hh = __float2bfloat16(val);
        g_ygh[off] = hh;
        g_ygl[off] = __float2bfloat16(val - __bfloat162float(hh));
    }
}

// ---------------- residual + LayerNorm ------------------------------------
__global__ __launch_bounds__(256)
void ln_kernel(const float* __restrict__ x, const float* __restrict__ gamma,
               const float* __restrict__ beta, float* __restrict__ out)
{
    const int m = blockIdx.x;
    __shared__ float buf[DMODEL];
    __shared__ float rs[2][8];
    float s1 = 0.0f, s2 = 0.0f;
#pragma unroll
    for (int i = 0; i < 4; i++) {
        int d = threadIdx.x + i*256;
        float v = g_tmp[(size_t)m*DMODEL + d] + x[(size_t)m*DMODEL + d];
        buf[d] = v;
        s1 += v; s2 += v*v;
    }
#pragma unroll
    for (int o = 16; o; o >>= 1) {
        s1 += __shfl_xor_sync(0xFFFFFFFFu, s1, o);
        s2 += __shfl_xor_sync(0xFFFFFFFFu, s2, o);
    }
    int w = threadIdx.x >> 5, lane = threadIdx.x & 31;
    if (lane == 0) { rs[0][w] = s1; rs[1][w] = s2; }
    __syncthreads();
    if (threadIdx.x == 0) {
        float a = 0.0f, b2 = 0.0f;
#pragma unroll
        for (int k = 0; k < 8; k++) { a += rs[0][k]; b2 += rs[1][k]; }
        rs[0][0] = a; rs[1][0] = b2;
    }
    __syncthreads();
    float mu  = rs[0][0] * (1.0f/DMODEL);
    float var = rs[1][0] * (1.0f/DMODEL) - mu*mu;
    float rstd = rsqrtf(var + 1e-5f);
#pragma unroll
    for (int i = 0; i < 4; i++) {
        int d = threadIdx.x + i*256;
        float v = buf[d];
        out[(size_t)m*DMODEL + d] = (v - mu)*rstd*gamma[d] + beta[d];
    }
}

// ---------------- launcher -------------------------------------------------
extern "C" void kernel_launch(void* const* d_in, const int* in_sizes, int n_in,
                              void* d_out, int out_size)
{
    const float* x       = (const float*)d_in[0];
    const float* W_in    = (const float*)d_in[1];
    const float* W_conv  = (const float*)d_in[2];
    const float* b_conv  = (const float*)d_in[3];
    const float* W_xproj = (const float*)d_in[4];
    const float* W_dt    = (const float*)d_in[5];
    const float* b_dt    = (const float*)d_in[6];
    const float* A_log   = (const float*)d_in[7];
    const float* D_skip  = (const float*)d_in[8];
    const float* W_out   = (const float*)d_in[9];
    const float* gamma   = (const float*)d_in[10];
    const float* beta    = (const float*)d_in[11];
    float* out = (float*)d_out;

    float *p_xz, *p_u, *p_xdb, *p_delta, *p_tmp;
    __nv_bfloat16 *p_xhi, *p_xlo, *p_wih, *p_wil, *p_woh, *p_wol, *p_ygh, *p_ygl;
    cudaGetSymbolAddress((void**)&p_xz,    g_xz);
    cudaGetSymbolAddress((void**)&p_u,     g_u);
    cudaGetSymbolAddress((void**)&p_xdb,   g_xdb);
    cudaGetSymbolAddress((void**)&p_delta, g_delta);
    cudaGetSymbolAddress((void**)&p_tmp,   g_tmp);
    cudaGetSymbolAddress((void**)&p_xhi,   g_xhi);
    cudaGetSymbolAddress((void**)&p_xlo,   g_xlo);
    cudaGetSymbolAddress((void**)&p_wih,   g_wih);
    cudaGetSymbolAddress((void**)&p_wil,   g_wil);
    cudaGetSymbolAddress((void**)&p_woh,   g_woh);
    cudaGetSymbolAddress((void**)&p_wol,   g_wol);
    cudaGetSymbolAddress((void**)&p_ygh,   g_ygh);
    cudaGetSymbolAddress((void**)&p_ygl,   g_ygl);

    cudaFuncSetAttribute(hmma_gemm, cudaFuncAttributeMaxDynamicSharedMemorySize,
                         HG_SMEM);

    // 0) fp32 -> bf16 hi/lo conversions
    cvt_kernel<<<(M_TOK*DMODEL/4 + 255)/256, 256>>>(x, p_xhi, p_xlo, M_TOK*DMODEL/4);
    cvt_kernel<<<(XZCOLS*DMODEL/4 + 255)/256, 256>>>(W_in, p_wih, p_wil, XZCOLS*DMODEL/4);
    cvt_kernel<<<(DMODEL*DINNER/4 + 255)/256, 256>>>(W_out, p_woh, p_wol, DMODEL*DINNER/4);

    // 1) in_proj (tensor cores): xz[4096][4096] = x @ W_in^T
    hmma_gemm<<<dim3(32, 32), 256, HG_SMEM>>>(p_xhi, p_xlo, p_wih, p_wil,
                                              p_xz, DMODEL, XZCOLS);
    // 2) causal depthwise conv + SiLU -> u
    conv_silu_kernel<<<(M_TOK*DINNER)/256, 256>>>(W_conv, b_conv);
    // 3) x_proj: xdb[4096][96] = u @ W_xproj^T
    sgemm_g2<<<128, 256>>>(p_u, W_xproj, p_xdb);
    // 4) dt_proj + bias + softplus -> delta[4096][2048]
    sgemm128<1><<<dim3(32, 16), 256>>>(p_xdb, XDBCOLS, W_dt, DTRANK, b_dt,
                                       p_delta, DINNER, DTRANK);
    // 5) selective scan (chunked) + gate (writes yg as bf16 hi/lo)
    scan_chunk_kernel<<<BATCH*NCHUNK*16, 128>>>(A_log);
    scan_prefix_kernel<<<(BATCH*DINNER*DSTATE)/256, 256>>>();
    scan_apply_kernel<<<BATCH*NCHUNK*16, 128>>>(A_log, D_skip);
    // 6) out_proj (tensor cores): tmp[4096][1024] = yg @ W_out^T
    hmma_gemm<<<dim3(32, 8), 256, HG_SMEM>>>(p_ygh, p_ygl, p_woh, p_wol,
                                             p_tmp, DINNER, DMODEL);
    // 7) residual + LayerNorm
    ln_kernel<<<M_TOK, 256>>>(x, gamma, beta, out);
}